// round 14
// baseline (speedup 1.0000x reference)
#include <cuda_runtime.h>
#include <cuda_bf16.h>
#include <cstdint>

// Problem constants
#define B_  4
#define T_  1024
#define D_  512
#define C_  8
#define H_  8
#define HD_ 64
#define BT_ (B_ * T_)      // 4096
#define D3_ (3 * D_)       // 1536

// Scratch (device globals: allocation-free, graph-capture safe)
__device__ float g_qkv[BT_ * D3_];            // [B*T, 3D] Q|K|V (fp32)
__device__ int   g_assign[BT_];               // cluster id per token
__device__ int   g_idx[B_ * C_ * T_];         // compacted token indices per (b,c)
__device__ int   g_cnt[B_ * C_];              // cluster sizes
__device__ __nv_bfloat16 g_xs[BT_ * 1024];    // X split   [r][0:512)=hi [512:1024)=lo
__device__ __nv_bfloat16 g_wins[D3_ * 1024];  // Win split
__device__ __nv_bfloat16 g_wouts[D_ * 1024];  // Wout split
__device__ __nv_bfloat16 g_attnsp[BT_ * 1024];// attention output, split hi|lo

// ---------------------------------------------------------------------------
// Kernel 1: cluster scores + argmax (exact fp32; '>' keeps first max).
// ---------------------------------------------------------------------------
__global__ void assign_kernel(const float* __restrict__ X,
                              const float* __restrict__ Wc,
                              const float* __restrict__ bc)
{
    __shared__ float sWc[C_ * D_];
    __shared__ float sbc[C_];
    int tid = threadIdx.x; // 128
    for (int i = tid; i < C_ * D_; i += 128) sWc[i] = Wc[i];
    if (tid < C_) sbc[tid] = bc[tid];
    __syncthreads();

    int lane = tid & 31, w = tid >> 5;
    int token = blockIdx.x * 4 + w;
    const float* xr = X + (size_t)token * D_;

    float sc[C_];
#pragma unroll
    for (int c = 0; c < C_; c++) sc[c] = 0.f;
    for (int i = lane; i < D_; i += 32) {
        float x = xr[i];
#pragma unroll
        for (int c = 0; c < C_; c++) sc[c] += x * sWc[c * D_ + i];
    }
#pragma unroll
    for (int c = 0; c < C_; c++) {
#pragma unroll
        for (int off = 16; off > 0; off >>= 1)
            sc[c] += __shfl_xor_sync(0xffffffffu, sc[c], off);
    }
    if (lane == 0) {
        float best = sc[0] + sbc[0]; int bi = 0;
#pragma unroll
        for (int c = 1; c < C_; c++) {
            float v = sc[c] + sbc[c];
            if (v > best) { best = v; bi = c; }
        }
        g_assign[token] = bi;
    }
}

// ---------------------------------------------------------------------------
// Kernel 2: deterministic stream-compaction per (b, c).
// ---------------------------------------------------------------------------
__global__ void compact_kernel()
{
    int bc = blockIdx.x;            // b*C + c
    int b = bc >> 3, c = bc & 7;
    __shared__ int warpTot[8];
    __shared__ int sBase;
    int tid = threadIdx.x;          // 256
    int lane = tid & 31, wid = tid >> 5;
    if (tid == 0) sBase = 0;
    __syncthreads();

    for (int t0 = 0; t0 < T_; t0 += 256) {
        int t = t0 + tid;
        bool flag = (g_assign[b * T_ + t] == c);
        unsigned bal = __ballot_sync(0xffffffffu, flag);
        int myPos = __popc(bal & ((1u << lane) - 1u));
        if (lane == 0) warpTot[wid] = __popc(bal);
        __syncthreads();
        int pre = 0;
        for (int wv = 0; wv < wid; wv++) pre += warpTot[wv];
        if (flag) g_idx[bc * T_ + sBase + pre + myPos] = t;
        __syncthreads();
        if (tid == 0) {
            int tot = 0;
            for (int wv = 0; wv < 8; wv++) tot += warpTot[wv];
            sBase += tot;
        }
        __syncthreads();
    }
    if (tid == 0) g_cnt[bc] = sBase;
}

// ---------------------------------------------------------------------------
// Kernel 3: fp32 -> bf16 hi/lo split.  src [rows][512] -> dst [rows][1024].
// ---------------------------------------------------------------------------
__global__ void split_kernel(const float* __restrict__ src,
                             __nv_bfloat16* __restrict__ dst)
{
    int r = blockIdx.x;
    int k = threadIdx.x << 1;
    float2 x = *(const float2*)(src + (size_t)r * 512 + k);
    __nv_bfloat16 h0 = __float2bfloat16(x.x);
    __nv_bfloat16 h1 = __float2bfloat16(x.y);
    __nv_bfloat16 l0 = __float2bfloat16(x.x - __bfloat162float(h0));
    __nv_bfloat16 l1 = __float2bfloat16(x.y - __bfloat162float(h1));
    *(__nv_bfloat162*)(dst + (size_t)r * 1024 + k)       = __halves2bfloat162(h0, h1);
    *(__nv_bfloat162*)(dst + (size_t)r * 1024 + 512 + k) = __halves2bfloat162(l0, l1);
}

// ---------------------------------------------------------------------------
// Kernel 4: bf16 split-3x tensor-core GEMM, cp.async double-buffered.
//   Cmat[M,N] = A[M,:512]*W[N,:512]^T  as Ah*Wh + Ah*Wl + Al*Wh  (fp32 accum)
// Per k-tile (32 wide): load Ah|Al|Wh|Wl ONCE into smem, run all 3 mma terms.
// BN=128: 8 warps (2x4), warp tile 64x32. BN=64: 4 warps (2x2).
// ---------------------------------------------------------------------------
#define CP_ASYNC16(dst_u32, src_ptr) \
    asm volatile("cp.async.cg.shared.global [%0], [%1], 16;" \
                 :: "r"(dst_u32), "l"(src_ptr))

template<int BN, int NWARPS>
__global__ __launch_bounds__(NWARPS * 32) void mma_gemm_kernel(
    const __nv_bfloat16* __restrict__ A,
    const __nv_bfloat16* __restrict__ W,
    const float* __restrict__ bias,
    float* __restrict__ Cmat, int M, int N)
{
    extern __shared__ __align__(16) __nv_bfloat16 smem[];
    // per-stage layout (elems): Ah[128*40] Al[128*40] Wh[BN*40] Wl[BN*40]
    const int T_AH = 0;
    const int T_AL = 128 * 40;
    const int T_WH = 256 * 40;
    const int T_WL = 256 * 40 + BN * 40;
    const int STAGE = 256 * 40 + 2 * BN * 40;

    int tid = threadIdx.x;
    int lane = tid & 31, wid = tid >> 5;
    int mBase = blockIdx.y * 128, nBase = blockIdx.x * BN;
    int wm = (wid & 1) * 64;
    int wn = (wid >> 1) * 32;

    float acc[4][4][4];
#pragma unroll
    for (int i = 0; i < 4; i++)
#pragma unroll
        for (int j = 0; j < 4; j++)
#pragma unroll
            for (int r = 0; r < 4; r++) acc[i][j][r] = 0.f;

    int lr = (lane & 7) + ((lane >> 3) & 1) * 8;   // 0..15
    int lc = (lane >> 4) * 8;                      // 0 or 8

    const int NCHA = 128 * 4;         // 16B chunks per A tile
    const int NCHW = BN * 4;
    const int NCH  = 2 * NCHA + 2 * NCHW;

    // loader: fetch k-tile kt into stage s
    auto load_stage = [&](int s, int kt) {
        int k0 = kt * 32;
        __nv_bfloat16* st = smem + s * STAGE;
        for (int i = tid; i < NCH; i += NWARPS * 32) {
            const __nv_bfloat16* src;
            __nv_bfloat16* dst;
            if (i < NCHA) {                       // Ah
                int row = i >> 2, seg = (i & 3) * 8;
                src = A + (size_t)(mBase + row) * 1024 + k0 + seg;
                dst = st + T_AH + row * 40 + seg;
            } else if (i < 2 * NCHA) {            // Al
                int il = i - NCHA;
                int row = il >> 2, seg = (il & 3) * 8;
                src = A + (size_t)(mBase + row) * 1024 + 512 + k0 + seg;
                dst = st + T_AL + row * 40 + seg;
            } else if (i < 2 * NCHA + NCHW) {     // Wh
                int il = i - 2 * NCHA;
                int row = il >> 2, seg = (il & 3) * 8;
                src = W + (size_t)(nBase + row) * 1024 + k0 + seg;
                dst = st + T_WH + row * 40 + seg;
            } else {                              // Wl
                int il = i - 2 * NCHA - NCHW;
                int row = il >> 2, seg = (il & 3) * 8;
                src = W + (size_t)(nBase + row) * 1024 + 512 + k0 + seg;
                dst = st + T_WL + row * 40 + seg;
            }
            uint32_t d32 = (uint32_t)__cvta_generic_to_shared(dst);
            CP_ASYNC16(d32, src);
        }
        asm volatile("cp.async.commit_group;" ::: "memory");
    };

    load_stage(0, 0);

    for (int kt = 0; kt < 16; kt++) {
        int s = kt & 1;
        if (kt < 15) {
            load_stage(s ^ 1, kt + 1);
            asm volatile("cp.async.wait_group 1;" ::: "memory");
        } else {
            asm volatile("cp.async.wait_group 0;" ::: "memory");
        }
        __syncthreads();

        const __nv_bfloat16* st = smem + s * STAGE;
#pragma unroll
        for (int kk = 0; kk < 2; kk++) {
            uint32_t ah[4][4], al[4][4], bh[2][4], bl[2][4];
#pragma unroll
            for (int i = 0; i < 4; i++) {
                uint32_t adh = (uint32_t)__cvta_generic_to_shared(
                    st + T_AH + (wm + i * 16 + lr) * 40 + kk * 16 + lc);
                asm volatile(
                    "ldmatrix.sync.aligned.m8n8.x4.shared.b16 {%0,%1,%2,%3}, [%4];"
                    : "=r"(ah[i][0]), "=r"(ah[i][1]), "=r"(ah[i][2]), "=r"(ah[i][3])
                    : "r"(adh));
                uint32_t adl = (uint32_t)__cvta_generic_to_shared(
                    st + T_AL + (wm + i * 16 + lr) * 40 + kk * 16 + lc);
                asm volatile(
                    "ldmatrix.sync.aligned.m8n8.x4.shared.b16 {%0,%1,%2,%3}, [%4];"
                    : "=r"(al[i][0]), "=r"(al[i][1]), "=r"(al[i][2]), "=r"(al[i][3])
                    : "r"(adl));
            }
#pragma unroll
            for (int jj = 0; jj < 2; jj++) {
                uint32_t bdh = (uint32_t)__cvta_generic_to_shared(
                    st + T_WH + (wn + jj * 16 + lr) * 40 + kk * 16 + lc);
                asm volatile(
                    "ldmatrix.sync.aligned.m8n8.x4.shared.b16 {%0,%1,%2,%3}, [%4];"
                    : "=r"(bh[jj][0]), "=r"(bh[jj][1]), "=r"(bh[jj][2]), "=r"(bh[jj][3])
                    : "r"(bdh));
                uint32_t bdl = (uint32_t)__cvta_generic_to_shared(
                    st + T_WL + (wn + jj * 16 + lr) * 40 + kk * 16 + lc);
                asm volatile(
                    "ldmatrix.sync.aligned.m8n8.x4.shared.b16 {%0,%1,%2,%3}, [%4];"
                    : "=r"(bl[jj][0]), "=r"(bl[jj][1]), "=r"(bl[jj][2]), "=r"(bl[jj][3])
                    : "r"(bdl));
            }
#pragma unroll
            for (int i = 0; i < 4; i++) {
#pragma unroll
                for (int j = 0; j < 4; j++) {
                    uint32_t b0h = bh[j >> 1][j & 1], b1h = bh[j >> 1][2 + (j & 1)];
                    uint32_t b0l = bl[j >> 1][j & 1], b1l = bl[j >> 1][2 + (j & 1)];
                    asm volatile(
                        "mma.sync.aligned.m16n8k16.row.col.f32.bf16.bf16.f32 "
                        "{%0,%1,%2,%3}, {%4,%5,%6,%7}, {%8,%9}, {%0,%1,%2,%3};"
                        : "+f"(acc[i][j][0]), "+f"(acc[i][j][1]),
                          "+f"(acc[i][j][2]), "+f"(acc[i][j][3])
                        : "r"(ah[i][0]), "r"(ah[i][1]), "r"(ah[i][2]), "r"(ah[i][3]),
                          "r"(b0h), "r"(b1h));
                    asm volatile(
                        "mma.sync.aligned.m16n8k16.row.col.f32.bf16.bf16.f32 "
                        "{%0,%1,%2,%3}, {%4,%5,%6,%7}, {%8,%9}, {%0,%1,%2,%3};"
                        : "+f"(acc[i][j][0]), "+f"(acc[i][j][1]),
                          "+f"(acc[i][j][2]), "+f"(acc[i][j][3])
                        : "r"(ah[i][0]), "r"(ah[i][1]), "r"(ah[i][2]), "r"(ah[i][3]),
                          "r"(b0l), "r"(b1l));
                    asm volatile(
                        "mma.sync.aligned.m16n8k16.row.col.f32.bf16.bf16.f32 "
                        "{%0,%1,%2,%3}, {%4,%5,%6,%7}, {%8,%9}, {%0,%1,%2,%3};"
                        : "+f"(acc[i][j][0]), "+f"(acc[i][j][1]),
                          "+f"(acc[i][j][2]), "+f"(acc[i][j][3])
                        : "r"(al[i][0]), "r"(al[i][1]), "r"(al[i][2]), "r"(al[i][3]),
                          "r"(b0h), "r"(b1h));
                }
            }
        }
        __syncthreads();   // done reading stage s before it is overwritten
    }

    // Epilogue: c0=(g,t*2) c1=(g,t*2+1) c2=(g+8,t*2) c3=(g+8,t*2+1)
    int g = lane >> 2, t = lane & 3;
#pragma unroll
    for (int i = 0; i < 4; i++) {
        int r0 = mBase + wm + i * 16 + g;
#pragma unroll
        for (int j = 0; j < 4; j++) {
            int col = nBase + wn + j * 8 + t * 2;
            float b0 = bias[col], b1 = bias[col + 1];
            *(float2*)(Cmat + (size_t)r0 * N + col) =
                make_float2(acc[i][j][0] + b0, acc[i][j][1] + b1);
            *(float2*)(Cmat + (size_t)(r0 + 8) * N + col) =
                make_float2(acc[i][j][2] + b0, acc[i][j][3] + b1);
        }
    }
}

// ---------------------------------------------------------------------------
// Kernel 5: per-(b,c,h) compacted attention, 64-key tiles, tile-level online
// softmax, scores kept in REGISTERS (no sS smem array — that was the R13 OOB).
// 2 threads per query: phase 1 computes each score via shfl pair-reduce; the
// owning thread ((j&1)==half) banks it in sreg[j>>1]. Phase 2: one rescale
// per tile. Phase 3: each pair iteration recovers the partner's p with one
// shfl and accumulates two V rows. Rows >= nk are zero-filled (no 0*NaN on
// first tile). Zero-key correction l_init = T - n. Writes bf16 hi/lo split.
// ---------------------------------------------------------------------------
__global__ __launch_bounds__(128) void attn_kernel()
{
    int h  = blockIdx.x & 7;
    int bc = blockIdx.x >> 3;   // b*C + c
    int b  = bc >> 3;
    int n  = g_cnt[bc];
    int q0 = blockIdx.y << 6;   // 64 queries per block
    if (q0 >= n) return;

    int tid = threadIdx.x;
    int half = tid & 1;
    int qi = q0 + (tid >> 1);
    bool valid = qi < n;
    int tq = g_idx[bc * T_ + (valid ? qi : 0)];

    __shared__ float sK[64][68];
    __shared__ float sV[64][68];

    float4 q4[8];
    {
        const float4* qp = (const float4*)(g_qkv + (size_t)(b * T_ + tq) * D3_
                                           + h * HD_ + half * 32);
#pragma unroll
        for (int i = 0; i < 8; i++) q4[i] = qp[i];
    }
    float o[32];
#pragma unroll
    for (int d = 0; d < 32; d++) o[d] = 0.f;
    float m, l;
    if (n < T_) { m = 0.f; l = (float)(T_ - n); }
    else        { m = -3.0e38f; l = 0.f; }

    int r = tid >> 1;           // key row this thread loads (0..63)
    int cbase = half * 32;      // column base for K/V load & read

    float sreg[32];

    for (int kt = 0; kt < n; kt += 64) {
        int nk = min(64, n - kt);
        __syncthreads();
        {
            float4* dK = (float4*)&sK[r][cbase];
            float4* dV = (float4*)&sV[r][cbase];
            if (r < nk) {
                int tk = g_idx[bc * T_ + kt + r];
                const float4* kp = (const float4*)(g_qkv + (size_t)(b * T_ + tk) * D3_
                                                   + D_ + h * HD_ + cbase);
                const float4* vp = kp + (D_ / 4);
#pragma unroll
                for (int u = 0; u < 8; u++) { dK[u] = kp[u]; dV[u] = vp[u]; }
            } else {
                float4 z = make_float4(0.f, 0.f, 0.f, 0.f);
#pragma unroll
                for (int u = 0; u < 8; u++) { dK[u] = z; dV[u] = z; }
            }
        }
        __syncthreads();

        // Phase 1: all scores for this tile; owner banks s in registers
        float tmax = -3.0e38f;
#pragma unroll
        for (int jj = 0; jj < 32; jj++) sreg[jj] = -3.0e38f;
        for (int j = 0; j < nk; j++) {
            const float4* kr = (const float4*)&sK[j][cbase];
            float s = 0.f;
#pragma unroll
            for (int i = 0; i < 8; i++) {
                float4 kv = kr[i];
                s += q4[i].x * kv.x + q4[i].y * kv.y +
                     q4[i].z * kv.z + q4[i].w * kv.w;
            }
            s += __shfl_xor_sync(0xffffffffu, s, 1);
            s *= 0.125f;  // 1/sqrt(64)
            tmax = fmaxf(tmax, s);
            if ((j & 1) == half) sreg[j >> 1] = s;
        }

        // Phase 2: one rescale per tile
        float m_new = fmaxf(m, tmax);
        if (m_new > m) {
            float corr = __expf(m - m_new);
            l *= corr;
#pragma unroll
            for (int d = 0; d < 32; d++) o[d] *= corr;
            m = m_new;
        }

        // Phase 3: pairwise exp + accumulate (partner's p via shfl)
        int jjmax = (nk + 1) >> 1;
        for (int jj = 0; jj < jjmax; jj++) {
            float pS = __expf(sreg[jj] - m);            // p for j = 2*jj + half
            float pO = __shfl_xor_sync(0xffffffffu, pS, 1); // partner's j
            int jS = 2 * jj + half;
            int jO = 2 * jj + (1 - half);
            l += pS + pO;
            const float4* vS = (const float4*)&sV[jS][cbase];
            const float4* vO = (const float4*)&sV[jO][cbase];
#pragma unroll
            for (int i = 0; i < 8; i++) {
                float4 a = vS[i], c2 = vO[i];
                o[4 * i + 0] += pS * a.x + pO * c2.x;
                o[4 * i + 1] += pS * a.y + pO * c2.y;
                o[4 * i + 2] += pS * a.z + pO * c2.z;
                o[4 * i + 3] += pS * a.w + pO * c2.w;
            }
        }
    }

    if (valid) {
        float inv = 1.f / l;
        size_t row = (size_t)(b * T_ + tq);
        __nv_bfloat16* hp = g_attnsp + row * 1024 + h * HD_ + half * 32;
        __nv_bfloat16* lp = hp + 512;
#pragma unroll
        for (int d = 0; d < 32; d += 2) {
            float v0 = o[d] * inv, v1 = o[d + 1] * inv;
            __nv_bfloat16 h0 = __float2bfloat16(v0);
            __nv_bfloat16 h1 = __float2bfloat16(v1);
            __nv_bfloat16 l0 = __float2bfloat16(v0 - __bfloat162float(h0));
            __nv_bfloat16 l1 = __float2bfloat16(v1 - __bfloat162float(h1));
            *(__nv_bfloat162*)(hp + d) = __halves2bfloat162(h0, h1);
            *(__nv_bfloat162*)(lp + d) = __halves2bfloat162(l0, l1);
        }
    }
}

// ---------------------------------------------------------------------------
extern "C" void kernel_launch(void* const* d_in, const int* in_sizes, int n_in,
                              void* d_out, int out_size)
{
    (void)in_sizes; (void)n_in; (void)out_size;
    const float* X    = (const float*)d_in[0];
    const float* Wc   = (const float*)d_in[1];
    const float* bc   = (const float*)d_in[2];
    const float* Win  = (const float*)d_in[3];
    const float* bin  = (const float*)d_in[4];
    const float* Wout = (const float*)d_in[5];
    const float* bout = (const float*)d_in[6];
    float* out = (float*)d_out;

    float* qkv = nullptr;
    __nv_bfloat16 *xs = nullptr, *wins = nullptr, *wouts = nullptr, *attnsp = nullptr;
    cudaGetSymbolAddress((void**)&qkv,    g_qkv);
    cudaGetSymbolAddress((void**)&xs,     g_xs);
    cudaGetSymbolAddress((void**)&wins,   g_wins);
    cudaGetSymbolAddress((void**)&wouts,  g_wouts);
    cudaGetSymbolAddress((void**)&attnsp, g_attnsp);

    // dynamic smem: BN=128 -> 81920 B; BN=64 -> 61440 B
    const int SM128 = 2 * (256 * 40 + 2 * 128 * 40) * 2;
    const int SM64  = 2 * (256 * 40 + 2 * 64 * 40) * 2;
    cudaFuncSetAttribute(mma_gemm_kernel<128, 8>,
                         cudaFuncAttributeMaxDynamicSharedMemorySize, SM128);
    cudaFuncSetAttribute(mma_gemm_kernel<64, 4>,
                         cudaFuncAttributeMaxDynamicSharedMemorySize, SM64);

    // 1) cluster argmax (exact fp32)
    assign_kernel<<<BT_ / 4, 128>>>(X, Wc, bc);
    // 2) compact indices per (b,c)
    compact_kernel<<<B_ * C_, 256>>>();
    // 3) bf16 hi/lo splits
    split_kernel<<<BT_, 256>>>(X, xs);
    split_kernel<<<D3_, 256>>>(Win, wins);
    split_kernel<<<D_, 256>>>(Wout, wouts);
    // 4) QKV projection: [4096,512] @ [512,1536]^T  (split-3x tensor cores)
    mma_gemm_kernel<128, 8><<<dim3(D3_ / 128, BT_ / 128), 256, SM128>>>(
        xs, wins, bin, qkv, BT_, D3_);
    // 5) per-cluster attention (fp32 softmax path, writes split bf16)
    attn_kernel<<<dim3(B_ * C_ * H_, T_ / 64), 128>>>();
    // 6) out projection: [4096,512] @ [512,512]^T  (BN=64 -> 256 blocks)
    mma_gemm_kernel<64, 4><<<dim3(D_ / 64, BT_ / 128), 128, SM64>>>(
        attnsp, wouts, bout, out, BT_, D_);
}

// round 17
// speedup vs baseline: 1.1567x; 1.1567x over previous
#include <cuda_runtime.h>
#include <cuda_bf16.h>
#include <cstdint>

// Problem constants
#define B_  4
#define T_  1024
#define D_  512
#define C_  8
#define H_  8
#define HD_ 64
#define BT_ (B_ * T_)      // 4096
#define D3_ (3 * D_)       // 1536

// Scratch (device globals: allocation-free, graph-capture safe)
__device__ float g_qkv[BT_ * D3_];            // [B*T, 3D] Q|K|V (fp32)
__device__ int   g_assign[BT_];               // cluster id per token
__device__ int   g_idx[B_ * C_ * T_];         // compacted token indices per (b,c)
__device__ int   g_cnt[B_ * C_];              // cluster sizes
__device__ __nv_bfloat16 g_xs[BT_ * 1024];    // X split   [r][0:512)=hi [512:1024)=lo
__device__ __nv_bfloat16 g_wins[D3_ * 1024];  // Win split
__device__ __nv_bfloat16 g_wouts[D_ * 1024];  // Wout split
__device__ __nv_bfloat16 g_attnsp[BT_ * 1024];// attention output, split hi|lo

// ---------------------------------------------------------------------------
// Kernel 1: cluster scores + argmax (exact fp32; '>' keeps first max).
// ---------------------------------------------------------------------------
__global__ void assign_kernel(const float* __restrict__ X,
                              const float* __restrict__ Wc,
                              const float* __restrict__ bc)
{
    __shared__ float sWc[C_ * D_];
    __shared__ float sbc[C_];
    int tid = threadIdx.x; // 128
    for (int i = tid; i < C_ * D_; i += 128) sWc[i] = Wc[i];
    if (tid < C_) sbc[tid] = bc[tid];
    __syncthreads();

    int lane = tid & 31, w = tid >> 5;
    int token = blockIdx.x * 4 + w;
    const float* xr = X + (size_t)token * D_;

    float sc[C_];
#pragma unroll
    for (int c = 0; c < C_; c++) sc[c] = 0.f;
    for (int i = lane; i < D_; i += 32) {
        float x = xr[i];
#pragma unroll
        for (int c = 0; c < C_; c++) sc[c] += x * sWc[c * D_ + i];
    }
#pragma unroll
    for (int c = 0; c < C_; c++) {
#pragma unroll
        for (int off = 16; off > 0; off >>= 1)
            sc[c] += __shfl_xor_sync(0xffffffffu, sc[c], off);
    }
    if (lane == 0) {
        float best = sc[0] + sbc[0]; int bi = 0;
#pragma unroll
        for (int c = 1; c < C_; c++) {
            float v = sc[c] + sbc[c];
            if (v > best) { best = v; bi = c; }
        }
        g_assign[token] = bi;
    }
}

// ---------------------------------------------------------------------------
// Kernel 2: deterministic stream-compaction per (b, c).
// ---------------------------------------------------------------------------
__global__ void compact_kernel()
{
    int bc = blockIdx.x;            // b*C + c
    int b = bc >> 3, c = bc & 7;
    __shared__ int warpTot[8];
    __shared__ int sBase;
    int tid = threadIdx.x;          // 256
    int lane = tid & 31, wid = tid >> 5;
    if (tid == 0) sBase = 0;
    __syncthreads();

    for (int t0 = 0; t0 < T_; t0 += 256) {
        int t = t0 + tid;
        bool flag = (g_assign[b * T_ + t] == c);
        unsigned bal = __ballot_sync(0xffffffffu, flag);
        int myPos = __popc(bal & ((1u << lane) - 1u));
        if (lane == 0) warpTot[wid] = __popc(bal);
        __syncthreads();
        int pre = 0;
        for (int wv = 0; wv < wid; wv++) pre += warpTot[wv];
        if (flag) g_idx[bc * T_ + sBase + pre + myPos] = t;
        __syncthreads();
        if (tid == 0) {
            int tot = 0;
            for (int wv = 0; wv < 8; wv++) tot += warpTot[wv];
            sBase += tot;
        }
        __syncthreads();
    }
    if (tid == 0) g_cnt[bc] = sBase;
}

// ---------------------------------------------------------------------------
// Kernel 3: merged fp32 -> bf16 hi/lo split for X, Win, Wout (one launch).
// Item = one float2 (2 elems). Grid-stride.
// ---------------------------------------------------------------------------
__global__ void split_all_kernel(const float* __restrict__ X,
                                 const float* __restrict__ Win,
                                 const float* __restrict__ Wout)
{
    const int TOT = (BT_ + D3_ + D_) * 256;   // 256 float2 per row
    for (int idx = blockIdx.x * blockDim.x + threadIdx.x; idx < TOT;
         idx += gridDim.x * blockDim.x) {
        int row = idx >> 8;
        int k = (idx & 255) << 1;
        const float* src;
        __nv_bfloat16* dst;
        if (row < BT_) {
            src = X + (size_t)row * 512;
            dst = g_xs + (size_t)row * 1024;
        } else if (row < BT_ + D3_) {
            int r = row - BT_;
            src = Win + (size_t)r * 512;
            dst = g_wins + (size_t)r * 1024;
        } else {
            int r = row - BT_ - D3_;
            src = Wout + (size_t)r * 512;
            dst = g_wouts + (size_t)r * 1024;
        }
        float2 x = *(const float2*)(src + k);
        __nv_bfloat16 h0 = __float2bfloat16(x.x);
        __nv_bfloat16 h1 = __float2bfloat16(x.y);
        __nv_bfloat16 l0 = __float2bfloat16(x.x - __bfloat162float(h0));
        __nv_bfloat16 l1 = __float2bfloat16(x.y - __bfloat162float(h1));
        *(__nv_bfloat162*)(dst + k)       = __halves2bfloat162(h0, h1);
        *(__nv_bfloat162*)(dst + 512 + k) = __halves2bfloat162(l0, l1);
    }
}

// ---------------------------------------------------------------------------
// Kernel 4: bf16 split-3x tensor-core GEMM, single-buffer, single-load.
//   Cmat[M,N] = A[M,:512]*W[N,:512]^T  as Ah*Wh + Ah*Wl + Al*Wh  (fp32 accum)
// Per 32-wide k-tile: load Ah|Al|Wh|Wl ONCE (sync LDG/STS), run all 3 terms.
// Inner loop streams A fragments (only 8 A regs live) to keep regs <= 128
// so MINB CTAs/SM co-reside and hide the synchronous loads.
// ---------------------------------------------------------------------------
template<int BN, int NWARPS, int MINB>
__global__ __launch_bounds__(NWARPS * 32, MINB) void mma_gemm_kernel(
    const __nv_bfloat16* __restrict__ A,
    const __nv_bfloat16* __restrict__ W,
    const float* __restrict__ bias,
    float* __restrict__ Cmat, int M, int N)
{
    __shared__ __nv_bfloat16 sm[(256 + 2 * BN) * 40];
    const int T_AH = 0;
    const int T_AL = 128 * 40;
    const int T_WH = 256 * 40;
    const int T_WL = (256 + BN) * 40;

    int tid = threadIdx.x;
    int lane = tid & 31, wid = tid >> 5;
    int mBase = blockIdx.y * 128, nBase = blockIdx.x * BN;
    int wm = (wid & 1) * 64;
    int wn = (wid >> 1) * 32;

    float acc[4][4][4];
#pragma unroll
    for (int i = 0; i < 4; i++)
#pragma unroll
        for (int j = 0; j < 4; j++)
#pragma unroll
            for (int r = 0; r < 4; r++) acc[i][j][r] = 0.f;

    int lr = (lane & 7) + ((lane >> 3) & 1) * 8;   // 0..15
    int lc = (lane >> 4) * 8;                      // 0 or 8

    const int NCH = (256 + 2 * BN) * 4;            // 16B chunks per k-tile

    for (int kt = 0; kt < 16; kt++) {
        int k0 = kt * 32;
        __syncthreads();
        for (int i = tid; i < NCH; i += NWARPS * 32) {
            int urow = i >> 2, seg = (i & 3) * 8;
            const __nv_bfloat16* src;
            if (urow < 256) {                      // Ah rows 0..127, Al 128..255
                int row = urow & 127;
                int off = (urow < 128) ? k0 : (512 + k0);
                src = A + (size_t)(mBase + row) * 1024 + off + seg;
            } else {                               // Wh rows 0..BN-1, Wl next
                int ur = urow - 256;
                int row = ur & (BN - 1);
                int off = (ur < BN) ? k0 : (512 + k0);
                src = W + (size_t)(nBase + row) * 1024 + off + seg;
            }
            *(uint4*)&sm[urow * 40 + seg] = *(const uint4*)src;
        }
        __syncthreads();

#pragma unroll
        for (int kk = 0; kk < 2; kk++) {
            uint32_t bh[2][4], bl[2][4];
#pragma unroll
            for (int jj = 0; jj < 2; jj++) {
                uint32_t bdh = (uint32_t)__cvta_generic_to_shared(
                    sm + T_WH + (wn + jj * 16 + lr) * 40 + kk * 16 + lc);
                asm volatile(
                    "ldmatrix.sync.aligned.m8n8.x4.shared.b16 {%0,%1,%2,%3}, [%4];"
                    : "=r"(bh[jj][0]), "=r"(bh[jj][1]), "=r"(bh[jj][2]), "=r"(bh[jj][3])
                    : "r"(bdh));
                uint32_t bdl = (uint32_t)__cvta_generic_to_shared(
                    sm + T_WL + (wn + jj * 16 + lr) * 40 + kk * 16 + lc);
                asm volatile(
                    "ldmatrix.sync.aligned.m8n8.x4.shared.b16 {%0,%1,%2,%3}, [%4];"
                    : "=r"(bl[jj][0]), "=r"(bl[jj][1]), "=r"(bl[jj][2]), "=r"(bl[jj][3])
                    : "r"(bdl));
            }
#pragma unroll
            for (int i = 0; i < 4; i++) {
                uint32_t ah[4];
                uint32_t adh = (uint32_t)__cvta_generic_to_shared(
                    sm + T_AH + (wm + i * 16 + lr) * 40 + kk * 16 + lc);
                asm volatile(
                    "ldmatrix.sync.aligned.m8n8.x4.shared.b16 {%0,%1,%2,%3}, [%4];"
                    : "=r"(ah[0]), "=r"(ah[1]), "=r"(ah[2]), "=r"(ah[3])
                    : "r"(adh));
#pragma unroll
                for (int j = 0; j < 4; j++) {
                    uint32_t b0h = bh[j >> 1][j & 1], b1h = bh[j >> 1][2 + (j & 1)];
                    uint32_t b0l = bl[j >> 1][j & 1], b1l = bl[j >> 1][2 + (j & 1)];
                    asm volatile(
                        "mma.sync.aligned.m16n8k16.row.col.f32.bf16.bf16.f32 "
                        "{%0,%1,%2,%3}, {%4,%5,%6,%7}, {%8,%9}, {%0,%1,%2,%3};"
                        : "+f"(acc[i][j][0]), "+f"(acc[i][j][1]),
                          "+f"(acc[i][j][2]), "+f"(acc[i][j][3])
                        : "r"(ah[0]), "r"(ah[1]), "r"(ah[2]), "r"(ah[3]),
                          "r"(b0h), "r"(b1h));
                    asm volatile(
                        "mma.sync.aligned.m16n8k16.row.col.f32.bf16.bf16.f32 "
                        "{%0,%1,%2,%3}, {%4,%5,%6,%7}, {%8,%9}, {%0,%1,%2,%3};"
                        : "+f"(acc[i][j][0]), "+f"(acc[i][j][1]),
                          "+f"(acc[i][j][2]), "+f"(acc[i][j][3])
                        : "r"(ah[0]), "r"(ah[1]), "r"(ah[2]), "r"(ah[3]),
                          "r"(b0l), "r"(b1l));
                }
                uint32_t al[4];
                uint32_t adl = (uint32_t)__cvta_generic_to_shared(
                    sm + T_AL + (wm + i * 16 + lr) * 40 + kk * 16 + lc);
                asm volatile(
                    "ldmatrix.sync.aligned.m8n8.x4.shared.b16 {%0,%1,%2,%3}, [%4];"
                    : "=r"(al[0]), "=r"(al[1]), "=r"(al[2]), "=r"(al[3])
                    : "r"(adl));
#pragma unroll
                for (int j = 0; j < 4; j++) {
                    uint32_t b0h = bh[j >> 1][j & 1], b1h = bh[j >> 1][2 + (j & 1)];
                    asm volatile(
                        "mma.sync.aligned.m16n8k16.row.col.f32.bf16.bf16.f32 "
                        "{%0,%1,%2,%3}, {%4,%5,%6,%7}, {%8,%9}, {%0,%1,%2,%3};"
                        : "+f"(acc[i][j][0]), "+f"(acc[i][j][1]),
                          "+f"(acc[i][j][2]), "+f"(acc[i][j][3])
                        : "r"(al[0]), "r"(al[1]), "r"(al[2]), "r"(al[3]),
                          "r"(b0h), "r"(b1h));
                }
            }
        }
    }

    // Epilogue: c0=(g,t*2) c1=(g,t*2+1) c2=(g+8,t*2) c3=(g+8,t*2+1)
    int g = lane >> 2, t = lane & 3;
#pragma unroll
    for (int i = 0; i < 4; i++) {
        int r0 = mBase + wm + i * 16 + g;
#pragma unroll
        for (int j = 0; j < 4; j++) {
            int col = nBase + wn + j * 8 + t * 2;
            float b0 = bias[col], b1 = bias[col + 1];
            *(float2*)(Cmat + (size_t)r0 * N + col) =
                make_float2(acc[i][j][0] + b0, acc[i][j][1] + b1);
            *(float2*)(Cmat + (size_t)(r0 + 8) * N + col) =
                make_float2(acc[i][j][2] + b0, acc[i][j][3] + b1);
        }
    }
}

// ---------------------------------------------------------------------------
// Kernel 5: per-(b,c,h) compacted attention (R8 version — known good/fast).
// 2 threads per query, 32-key tiles, per-key online softmax via full-mask
// shfl pair-reduce; only the final store is predicated. Zero-key correction
// l_init = T - n. Writes bf16 hi/lo split (out-proj A operand).
// ---------------------------------------------------------------------------
#define PADC(c) ((c) + (((c) >> 5) << 2))
__global__ __launch_bounds__(128) void attn_kernel()
{
    int h  = blockIdx.x & 7;
    int bc = blockIdx.x >> 3;   // b*C + c
    int b  = bc >> 3;
    int n  = g_cnt[bc];
    int q0 = blockIdx.y << 6;   // 64 queries per block
    if (q0 >= n) return;

    int tid = threadIdx.x;
    int half = tid & 1;
    int qi = q0 + (tid >> 1);
    bool valid = qi < n;
    int tq = g_idx[bc * T_ + (valid ? qi : 0)];

    __shared__ float sK[32][68];
    __shared__ float sV[32][68];

    float4 q4[8];
    {
        const float4* qp = (const float4*)(g_qkv + (size_t)(b * T_ + tq) * D3_
                                           + h * HD_ + half * 32);
#pragma unroll
        for (int i = 0; i < 8; i++) q4[i] = qp[i];
    }
    float o[32];
#pragma unroll
    for (int d = 0; d < 32; d++) o[d] = 0.f;
    float m, l;
    if (n < T_) { m = 0.f; l = (float)(T_ - n); }
    else        { m = -3.0e38f; l = 0.f; }

    int r = tid >> 2;                 // key row 0..31
    int part = (tid & 3) << 4;        // 0,16,32,48 floats
    int rbase = half * 36;            // padded read base

    for (int kt = 0; kt < n; kt += 32) {
        int nk = min(32, n - kt);
        __syncthreads();
        if (r < nk) {
            int tk = g_idx[bc * T_ + kt + r];
            const float4* kp = (const float4*)(g_qkv + (size_t)(b * T_ + tk) * D3_
                                               + D_ + h * HD_ + part);
            const float4* vp = kp + (D_ / 4);
            float4* dK = (float4*)&sK[r][PADC(part)];
            float4* dV = (float4*)&sV[r][PADC(part)];
#pragma unroll
            for (int u = 0; u < 4; u++) {
                dK[u] = kp[u];
                dV[u] = vp[u];
            }
        }
        __syncthreads();
        for (int j = 0; j < nk; j++) {
            const float4* kr = (const float4*)&sK[j][rbase];
            float s = 0.f;
#pragma unroll
            for (int i = 0; i < 8; i++) {
                float4 kv = kr[i];
                s += q4[i].x * kv.x + q4[i].y * kv.y +
                     q4[i].z * kv.z + q4[i].w * kv.w;
            }
            s += __shfl_xor_sync(0xffffffffu, s, 1);
            s *= 0.125f;  // 1/sqrt(64)
            if (s > m) {
                float corr = __expf(m - s);
                l *= corr;
#pragma unroll
                for (int d = 0; d < 32; d++) o[d] *= corr;
                m = s;
            }
            float p = __expf(s - m);
            l += p;
            const float4* vr = (const float4*)&sV[j][rbase];
#pragma unroll
            for (int i = 0; i < 8; i++) {
                float4 vv = vr[i];
                o[4 * i + 0] += p * vv.x;
                o[4 * i + 1] += p * vv.y;
                o[4 * i + 2] += p * vv.z;
                o[4 * i + 3] += p * vv.w;
            }
        }
    }

    if (valid) {
        float inv = 1.f / l;
        size_t row = (size_t)(b * T_ + tq);
        __nv_bfloat16* hp = g_attnsp + row * 1024 + h * HD_ + half * 32;
        __nv_bfloat16* lp = hp + 512;
#pragma unroll
        for (int d = 0; d < 32; d += 2) {
            float v0 = o[d] * inv, v1 = o[d + 1] * inv;
            __nv_bfloat16 h0 = __float2bfloat16(v0);
            __nv_bfloat16 h1 = __float2bfloat16(v1);
            __nv_bfloat16 l0 = __float2bfloat16(v0 - __bfloat162float(h0));
            __nv_bfloat16 l1 = __float2bfloat16(v1 - __bfloat162float(h1));
            *(__nv_bfloat162*)(hp + d) = __halves2bfloat162(h0, h1);
            *(__nv_bfloat162*)(lp + d) = __halves2bfloat162(l0, l1);
        }
    }
}

// ---------------------------------------------------------------------------
extern "C" void kernel_launch(void* const* d_in, const int* in_sizes, int n_in,
                              void* d_out, int out_size)
{
    (void)in_sizes; (void)n_in; (void)out_size;
    const float* X    = (const float*)d_in[0];
    const float* Wc   = (const float*)d_in[1];
    const float* bc   = (const float*)d_in[2];
    const float* Win  = (const float*)d_in[3];
    const float* bin  = (const float*)d_in[4];
    const float* Wout = (const float*)d_in[5];
    const float* bout = (const float*)d_in[6];
    float* out = (float*)d_out;

    float* qkv = nullptr;
    __nv_bfloat16 *xs = nullptr, *wins = nullptr, *wouts = nullptr, *attnsp = nullptr;
    cudaGetSymbolAddress((void**)&qkv,    g_qkv);
    cudaGetSymbolAddress((void**)&xs,     g_xs);
    cudaGetSymbolAddress((void**)&wins,   g_wins);
    cudaGetSymbolAddress((void**)&wouts,  g_wouts);
    cudaGetSymbolAddress((void**)&attnsp, g_attnsp);

    // 1) cluster argmax (exact fp32)
    assign_kernel<<<BT_ / 4, 128>>>(X, Wc, bc);
    // 2) compact indices per (b,c)
    compact_kernel<<<B_ * C_, 256>>>();
    // 3) bf16 hi/lo splits (one merged launch)
    split_all_kernel<<<1184, 256>>>(X, Win, Wout);
    // 4) QKV projection: [4096,512] @ [512,1536]^T  (split-3x tensor cores)
    mma_gemm_kernel<128, 8, 2><<<dim3(D3_ / 128, BT_ / 128), 256>>>(
        xs, wins, bin, qkv, BT_, D3_);
    // 5) per-cluster attention (fp32 softmax path, writes split bf16)
    attn_kernel<<<dim3(B_ * C_ * H_, T_ / 64), 128>>>();
    // 6) out projection: [4096,512] @ [512,512]^T  (BN=64 -> 256 blocks)
    mma_gemm_kernel<64, 4, 4><<<dim3(D_ / 64, BT_ / 128), 128>>>(
        attnsp, wouts, bout, out, BT_, D_);
}